// round 2
// baseline (speedup 1.0000x reference)
#include <cuda_runtime.h>
#include <math.h>

#define KK 769      // 2M+1 states
#define MM 384      // latent length
#define BB 64
#define LL 256
#define AA 21
#define NEGV (-1.0e32f)

// ---------------- device scratch ----------------
__device__ float g_obs[AA * KK];   // normalized emission logits, transposed [a*KK+k]
__device__ float g_cm[KK];         // exp(direct-to-match-target - lse_row)   (per source)
__device__ float g_ci[KK];         // exp(direct-to-insert-target - lse_row)  (per source)
__device__ float g_cf[KK];         // exp(src_stay+src_del - lse_row)         (chain source weight)
__device__ float g_et[KK];         // exp(t_term[kp])                         (chain target weight)
__device__ float g_w[MM];          // w[j] = exp(d2[j])                       (chain decay)
__device__ float g_init[KK];       // normalized initial log-probs
__device__ int   g_letters[BB * LL];

// ---------------- prep: arrange + normalize all HMM constants ----------------
__global__ __launch_bounds__(512) void prep_kernel(
    const float* __restrict__ pre,   // (384,21)
    const float* __restrict__ iseq,  // (385,21)
    const float* __restrict__ ins,   // (384,3,2)
    const float* __restrict__ del)   // (384,3,2)
{
    __shared__ float lre[(MM + 1) * 3 * 2];
    __shared__ float lue[(MM + 1) * 3 * 2];
    __shared__ float sC[MM + 2];       // C[j] = sum_{i<j} d2[i]
    __shared__ float sW2[MM + 1];      // w2[j]=exp(d2[j]) j<M ; w2[M]=0
    __shared__ float sQt[MM + 1];      // Qt[m] = [m<M]exp(t_match[m]) + exp(t_ins[m])
    __shared__ float sG[MM + 1];       // G[s] = sum_{m>s} exp(C[m]-C[s+1]) Qt[m]
    __shared__ float WT[16], ST[16], FIN[16];
    __shared__ float sInit[KK];
    __shared__ float red[16];

    const int tid = threadIdx.x, lane = tid & 31, wid = tid >> 5;

    // 1. log-softmax of insert/delete (last dim size 2) + boundary rows (r_M=1, u_M=0)
    for (int idx = tid; idx < MM * 3; idx += 512) {
        float x0 = ins[idx * 2], x1 = ins[idx * 2 + 1];
        float mx = fmaxf(x0, x1);
        float l = mx + logf(expf(x0 - mx) + expf(x1 - mx));
        lre[idx * 2] = x0 - l; lre[idx * 2 + 1] = x1 - l;
        x0 = del[idx * 2]; x1 = del[idx * 2 + 1];
        mx = fmaxf(x0, x1);
        l = mx + logf(expf(x0 - mx) + expf(x1 - mx));
        lue[idx * 2] = x0 - l; lue[idx * 2 + 1] = x1 - l;
    }
    if (tid < 3) {
        lre[(MM * 3 + tid) * 2 + 0] = NEGV; lre[(MM * 3 + tid) * 2 + 1] = 0.f;
        lue[(MM * 3 + tid) * 2 + 0] = 0.f;  lue[(MM * 3 + tid) * 2 + 1] = NEGV;
    }
    __syncthreads();

    // 2. C = exclusive cumsum of d2 (log domain) ; also w2, Qt
    {
        float d2 = 0.f;
        if (tid < MM) d2 = lre[(tid * 3 + 2) * 2 + 0] + lue[(tid * 3 + 2) * 2 + 1];
        float inc = d2;
        #pragma unroll
        for (int o = 1; o < 32; o <<= 1) {
            float t = __shfl_up_sync(0xffffffffu, inc, o);
            if (lane >= o) inc += t;
        }
        if (lane == 31) WT[wid] = inc;
        __syncthreads();
        float off = 0.f;
        for (int j = 0; j < wid; j++) off += WT[j];
        if (tid < MM) { sC[tid + 1] = inc + off; sW2[tid] = expf(d2); }
        if (tid == 0) { sC[0] = 0.f; sC[MM + 1] = 0.f; sW2[MM] = 0.f; }
        if (tid <= MM) {
            float ti = lre[(tid * 3 + 2) * 2 + 1];
            float q = expf(ti);
            if (tid < MM) q += expf(lre[(tid * 3 + 2) * 2 + 0] + lue[(tid * 3 + 2) * 2 + 0]);
            sQt[tid] = q;
        }
        __syncthreads();
    }

    // 3. G via reverse affine scan: elements t=0..383, (A,B) = (w2[M-t], Qt[M-t]);
    //    inclusive result at t = G[M-1-t]; G[M]=0.
    {
        float A = 1.f, Bv = 0.f;
        if (tid < MM) { A = sW2[MM - tid]; Bv = sQt[MM - tid]; }
        #pragma unroll
        for (int o = 1; o < 32; o <<= 1) {
            float Wp = __shfl_up_sync(0xffffffffu, A, o);
            float Sp = __shfl_up_sync(0xffffffffu, Bv, o);
            if (lane >= o) { Bv = fmaf(A, Sp, Bv); A *= Wp; }
        }
        if (lane == 31 && wid < 12) { WT[wid] = A; ST[wid] = Bv; }
        __syncthreads();
        if (wid == 0) {
            float Wt = (lane < 12) ? WT[lane] : 1.f;
            float St = (lane < 12) ? ST[lane] : 0.f;
            #pragma unroll
            for (int o = 1; o < 16; o <<= 1) {
                float Wp = __shfl_up_sync(0xffffffffu, Wt, o);
                float Sp = __shfl_up_sync(0xffffffffu, St, o);
                if (lane >= o) { St = fmaf(Wt, Sp, St); Wt *= Wp; }
            }
            float e = __shfl_up_sync(0xffffffffu, St, 1);
            if (lane == 0) e = 0.f;
            if (lane < 12) FIN[lane] = e;
        }
        __syncthreads();
        if (tid < MM) sG[MM - 1 - tid] = fmaf(A, FIN[wid], Bv);
        if (tid == 0) sG[MM] = 0.f;
        __syncthreads();
    }

    // 4. per-state constants with analytic row logsumexp (all scale-free)
    for (int k = tid; k < KK; k += 512) {
        const int m = (k < MM) ? k : k - MM;
        const int g = (k < MM) ? 0 : 1;
        const int s = m + 1 - g;
        float src_stay  = lre[(s * 3 + g) * 2 + 0];
        float src_ins   = lre[(s * 3 + g) * 2 + 1];
        float src_match = lue[(s * 3 + g) * 2 + 0];
        float src_del   = lue[(s * 3 + g) * 2 + 1];
        float dmatch = src_stay + src_match;
        float dins = src_ins;
        float cflog = src_stay + src_del;
        float rowsum = expf(dins) + ((s < MM) ? expf(dmatch) : 0.f) + expf(cflog) * sG[s];
        float lse = logf(rowsum);
        g_cm[k] = expf(dmatch - lse);
        g_ci[k] = expf(dins - lse);
        g_cf[k] = expf(cflog - lse);
        float tterm = (g == 1) ? lre[(m * 3 + 2) * 2 + 1]
                               : (lre[(m * 3 + 2) * 2 + 0] + lue[(m * 3 + 2) * 2 + 0]);
        g_et[k] = expf(tterm);
        float initv;
        if (m == 0) initv = (g == 1) ? lre[1] : (lre[0] + lue[0]);
        else        initv = lre[0] + lue[1] - sC[1] + sC[m] + tterm;
        sInit[k] = initv;
    }
    if (tid < MM) g_w[tid] = sW2[tid];
    __syncthreads();

    // 5. normalize init (stable logsumexp over 769, log domain — underflow matches ref)
    {
        float mloc = -INFINITY;
        for (int k = tid; k < KK; k += 512) mloc = fmaxf(mloc, sInit[k]);
        #pragma unroll
        for (int o = 16; o; o >>= 1) mloc = fmaxf(mloc, __shfl_xor_sync(0xffffffffu, mloc, o));
        if (lane == 0) red[wid] = mloc;
        __syncthreads();
        float mxI = red[0];
        #pragma unroll
        for (int j = 1; j < 16; j++) mxI = fmaxf(mxI, red[j]);
        __syncthreads();
        float s0 = 0.f;
        for (int k = tid; k < KK; k += 512) s0 += expf(sInit[k] - mxI);
        #pragma unroll
        for (int o = 16; o; o >>= 1) s0 += __shfl_xor_sync(0xffffffffu, s0, o);
        if (lane == 0) red[wid] = s0;
        __syncthreads();
        float Z = 0.f;
        for (int j = 0; j < 16; j++) Z += red[j];
        float lz = mxI + logf(Z);
        for (int k = tid; k < KK; k += 512) g_init[k] = sInit[k] - lz;
    }

    // 6. emission logits, double-normalized over A, stored transposed
    for (int k = tid; k < KK; k += 512) {
        const float* row = (k < MM) ? (pre + k * AA) : (iseq + (k - MM) * AA);
        float mx = -INFINITY;
        for (int a = 0; a < AA; a++) mx = fmaxf(mx, row[a]);
        float sm = 0.f;
        for (int a = 0; a < AA; a++) sm += expf(row[a] - mx);
        float l = mx + logf(sm);
        float sm2 = 0.f;
        for (int a = 0; a < AA; a++) sm2 += expf(row[a] - l);
        float l2 = logf(sm2);
        for (int a = 0; a < AA; a++) g_obs[a * KK + k] = (row[a] - l) - l2;
    }
}

// ---------------- letters (or -1 for missing rows) ----------------
__global__ __launch_bounds__(LL) void letters_kernel(const float* __restrict__ seq)
{
    int b = blockIdx.x, l = threadIdx.x;
    const float* row = seq + ((size_t)b * LL + l) * AA;
    int let = -1;
    #pragma unroll
    for (int a = 0; a < AA; a++)
        if (row[a] > 0.5f) let = a;
    g_letters[b * LL + l] = let;
}

// ---------------- forward recursion: one CTA per batch ----------------
__global__ __launch_bounds__(512) void hmm_forward(const float* __restrict__ lscale,
                                                   float* __restrict__ out)
{
    __shared__ float s_alpha[KK];
    __shared__ float s_ea[KK];
    __shared__ float s_cm[KK], s_ci[KK], s_cf[KK], s_et[KK];
    __shared__ float s_w[MM];
    __shared__ float s_Ws[MM], s_Ss[MM];   // per-element inclusive affine scan state
    __shared__ float s_WT[16], s_ST[16];   // warp totals
    __shared__ float s_Fin[16];            // incoming F per warp
    __shared__ float s_wm[16];
    __shared__ int   s_let[LL];

    const int b = blockIdx.x, tid = threadIdx.x, lane = tid & 31, wid = tid >> 5;
    const bool has2 = tid < (KK - 512);

    for (int i = tid; i < KK; i += 512) {
        s_cm[i] = g_cm[i]; s_ci[i] = g_ci[i]; s_cf[i] = g_cf[i]; s_et[i] = g_et[i];
    }
    if (tid < MM) s_w[tid] = g_w[tid];
    for (int i = tid; i < LL; i += 512) s_let[i] = g_letters[b * LL + i];
    __syncthreads();

    {
        int l0 = s_let[0];
        const float* obr = g_obs + (l0 >= 0 ? l0 : 0) * KK;
        s_alpha[tid] = g_init[tid] + (l0 >= 0 ? obr[tid] : 0.f);
        if (has2) s_alpha[512 + tid] = g_init[512 + tid] + (l0 >= 0 ? obr[512 + tid] : 0.f);
    }
    __syncthreads();

    for (int t = 1; t < LL; t++) {
        // prefetch emission row (L2-resident; hidden behind the barrier phases)
        const int lt = s_let[t];
        const float* obr = g_obs + (lt >= 0 ? lt : 0) * KK;
        float vl0 = (lt >= 0) ? obr[tid] : 0.f;
        float vl1 = (has2 && lt >= 0) ? obr[512 + tid] : 0.f;

        // ---- 1. block max of alpha ----
        float lm = s_alpha[tid];
        if (has2) lm = fmaxf(lm, s_alpha[512 + tid]);
        #pragma unroll
        for (int o = 16; o; o >>= 1) lm = fmaxf(lm, __shfl_xor_sync(0xffffffffu, lm, o));
        if (lane == 0) s_wm[wid] = lm;
        __syncthreads();
        float mx = s_wm[0];
        #pragma unroll
        for (int j = 1; j < 16; j++) mx = fmaxf(mx, s_wm[j]);

        // ---- 2. ea = exp(alpha - mx) ----
        s_ea[tid] = __expf(s_alpha[tid] - mx);
        if (has2) s_ea[512 + tid] = __expf(s_alpha[512 + tid] - mx);
        __syncthreads();

        // ---- 3. affine scan: F[m+1] = w[m] F[m] + S_raw[m], over m=0..383 ----
        float Wv = 1.f, Sv = 0.f;
        if (tid < MM) {
            Wv = s_w[tid];
            Sv = s_ea[MM + tid] * s_cf[MM + tid];               // insert source, s_k = tid
            if (tid >= 1) Sv = fmaf(s_ea[tid - 1], s_cf[tid - 1], Sv);  // match source, s_k = tid
        }
        #pragma unroll
        for (int o = 1; o < 32; o <<= 1) {
            float Wp = __shfl_up_sync(0xffffffffu, Wv, o);
            float Sp = __shfl_up_sync(0xffffffffu, Sv, o);
            if (lane >= o) { Sv = fmaf(Wv, Sp, Sv); Wv *= Wp; }
        }
        if (tid < MM) { s_Ws[tid] = Wv; s_Ss[tid] = Sv; }
        if (lane == 31 && wid < 12) { s_WT[wid] = Wv; s_ST[wid] = Sv; }
        __syncthreads();
        if (wid == 0) {
            float Wt = (lane < 12) ? s_WT[lane] : 1.f;
            float St = (lane < 12) ? s_ST[lane] : 0.f;
            #pragma unroll
            for (int o = 1; o < 16; o <<= 1) {
                float Wp = __shfl_up_sync(0xffffffffu, Wt, o);
                float Sp = __shfl_up_sync(0xffffffffu, St, o);
                if (lane >= o) { St = fmaf(Wt, Sp, St); Wt *= Wp; }
            }
            float e = __shfl_up_sync(0xffffffffu, St, 1);
            if (lane == 0) e = 0.f;
            if (lane < 12) s_Fin[lane] = e;
        }
        __syncthreads();

        // ---- 4. per-target combine: 2 banded entries + chain term F[m]*et[kp] ----
        float na0, na1 = 0.f;
        {
            const int kp = tid;
            const bool insd = kp >= MM;
            const int m = insd ? kp - MM : kp;
            float fm = 0.f;
            if (m >= 1) { int j = m - 1; fm = fmaf(s_Ws[j], s_Fin[j >> 5], s_Ss[j]); }
            float pr = s_et[kp] * fm;
            const int k2 = MM + m;
            pr = fmaf(s_ea[k2], (insd ? s_ci[k2] : s_cm[k2]), pr);
            if (m >= 1) {
                const int k1 = m - 1;
                pr = fmaf(s_ea[k1], (insd ? s_ci[k1] : s_cm[k1]), pr);
            }
            na0 = __logf(fmaxf(pr, 1e-30f)) + mx + vl0;
        }
        if (has2) {
            const int kp = 512 + tid;  // insert state, m = kp-MM
            const int m = kp - MM;
            int j = m - 1;
            float fm = fmaf(s_Ws[j], s_Fin[j >> 5], s_Ss[j]);
            float pr = s_et[kp] * fm;
            pr = fmaf(s_ea[MM + m], s_ci[MM + m], pr);
            pr = fmaf(s_ea[m - 1], s_ci[m - 1], pr);
            na1 = __logf(fmaxf(pr, 1e-30f)) + mx + vl1;
        }
        s_alpha[tid] = na0;
        if (has2) s_alpha[512 + tid] = na1;
        __syncthreads();
    }

    // ---- final logsumexp over states ----
    float lm = s_alpha[tid];
    if (has2) lm = fmaxf(lm, s_alpha[512 + tid]);
    #pragma unroll
    for (int o = 16; o; o >>= 1) lm = fmaxf(lm, __shfl_xor_sync(0xffffffffu, lm, o));
    if (lane == 0) s_wm[wid] = lm;
    __syncthreads();
    float mx = s_wm[0];
    #pragma unroll
    for (int j = 1; j < 16; j++) mx = fmaxf(mx, s_wm[j]);
    float sm = __expf(s_alpha[tid] - mx);
    if (has2) sm += __expf(s_alpha[512 + tid] - mx);
    #pragma unroll
    for (int o = 16; o; o >>= 1) sm += __shfl_xor_sync(0xffffffffu, sm, o);
    if (lane == 0) s_WT[wid] = sm;
    __syncthreads();
    if (tid == 0) {
        float Z = 0.f;
        for (int j = 0; j < 16; j++) Z += s_WT[j];
        out[b] = lscale[0] * (mx + logf(Z));
    }
}

extern "C" void kernel_launch(void* const* d_in, const int* in_sizes, int n_in,
                              void* d_out, int out_size)
{
    const float* pre  = (const float*)d_in[0];   // precursor_seq (384,21)
    const float* iseq = (const float*)d_in[1];   // insert_seq (385,21)
    const float* ins  = (const float*)d_in[2];   // insert (384,3,2)
    const float* del  = (const float*)d_in[3];   // delete (384,3,2)
    const float* seq  = (const float*)d_in[4];   // seq_data (64,256,21)
    const float* ls   = (const float*)d_in[5];   // local_scale (1,)
    float* out = (float*)d_out;                  // (64,)

    prep_kernel<<<1, 512>>>(pre, iseq, ins, del);
    letters_kernel<<<BB, LL>>>(seq);
    hmm_forward<<<BB, 512>>>(ls, out);
}